// round 8
// baseline (speedup 1.0000x reference)
#include <cuda_runtime.h>
#include <cuda_bf16.h>
#include <math.h>
#include <stdint.h>

// Problem dims
#define B   512
#define T   512
#define L   64
#define H   512
#define G3  1536
#define XW  575
#define K512 512
#define BK   32
#define NIT  16           // K512 / BK
#define TM   64
#define TN   96           // 32 gate-triples per tile
// smem: A_hi 64*80, A_lo 64*80, B_hi 96*80, B_lo 96*80 = 25600 bytes.
// Epilogue aliases the same buffer as float S[64][100] = 25600 bytes.
#define ROWB 80
#define OFF_AHI 0
#define OFF_ALO 5120
#define OFF_BHI 10240
#define OFF_BLO 17920
#define SMEM_DYN 25600

// -------- device scratch --------
__device__ float g_GI1[(size_t)L * B * G3];    // permuted x-side gates, layer 1
__device__ float g_GH2[(size_t)B * G3];        // permuted h-side gates, layer 2
__device__ float g_h1x[2][(size_t)B * H];      // ping-pong hidden, layer 1
__device__ float g_h2x[2][(size_t)B * H];      // ping-pong hidden, layer 2
__device__ float g_H2A[(size_t)L * B * H];     // h2 history for FC head
// permuted weights (row' = 3j + gate) and biases
__device__ __align__(16) float g_Wih1p[(size_t)G3 * K512];
__device__ __align__(16) float g_Whh1p[(size_t)G3 * K512];
__device__ __align__(16) float g_Wih2p[(size_t)G3 * K512];
__device__ __align__(16) float g_Whh2p[(size_t)G3 * K512];
__device__ float g_bih1p[G3], g_bhh1p[G3], g_bih2p[G3], g_bhh2p[G3];

// ---------------- PTX helper ----------------
__device__ __forceinline__ void mma16816(float* d, const uint32_t* a, const uint32_t* b) {
    asm volatile(
        "mma.sync.aligned.m16n8k16.row.col.f32.bf16.bf16.f32 "
        "{%0,%1,%2,%3}, {%4,%5,%6,%7}, {%8,%9}, {%0,%1,%2,%3};"
        : "+f"(d[0]), "+f"(d[1]), "+f"(d[2]), "+f"(d[3])
        : "r"(a[0]), "r"(a[1]), "r"(a[2]), "r"(a[3]), "r"(b[0]), "r"(b[1]));
}
__device__ __forceinline__ float sigmoidf_(float v) { return 1.0f / (1.0f + expf(-v)); }

// ---------------------------------------------------------------
// 64x96 tile of A[.,K512] @ W[.,K512]^T (+bias) with in-smem fp32->
// (hi,lo) bf16 split and 3-term compensated mma (validated round 7).
// MODE 0: write C tile to gmem (ldc = G3).
// MODE 1: gate1 epilogue: acc=GH1, Gother=GI1p(t), hold->hout (layer 1).
// MODE 2: gate2 epilogue: acc=GI2, Gother=GH2,    hold->hout (+H2A).
// ---------------------------------------------------------------
template<int MODE>
__device__ void gemm96(const float* __restrict__ A, int lda,
                       const float* __restrict__ W,
                       const float* __restrict__ bias,
                       float* __restrict__ C,
                       const float* __restrict__ Gother,
                       const float* __restrict__ hold,
                       float* __restrict__ hout,
                       float* __restrict__ h2a)
{
    extern __shared__ __align__(128) char sm[];
    const int tid  = threadIdx.x;
    const int wid  = tid >> 5;
    const int lane = tid & 31;
    const int m0 = blockIdx.y * TM;
    const int n0 = blockIdx.x * TN;

    const int arow = tid >> 2;          // 0..63
    const int ac8  = (tid & 3) * 8;     // group of 8 floats within BK=32

    const int wm = (wid & 1) * 32;      // 2 warps over M=64
    const int wn = (wid >> 1) * 24;     // 4 warps over N=96
    const int r8 = lane >> 2;
    const int c2 = (lane & 3) * 2;

    float acc[2][3][4] = {};

    for (int it = 0; it < NIT; it++) {
        const int k = it * BK;

        // ---- load + split A row (8 floats / thread) ----
        {
            const float* ap = A + (size_t)(m0 + arow) * lda + k + ac8;
            __align__(16) __nv_bfloat16 hi[8], lo[8];
            #pragma unroll
            for (int i = 0; i < 8; i++) {
                const float v = ap[i];
                hi[i] = __float2bfloat16(v);
                lo[i] = __float2bfloat16(v - __bfloat162float(hi[i]));
            }
            *(uint4*)(sm + OFF_AHI + arow * ROWB + ac8 * 2) = *(const uint4*)hi;
            *(uint4*)(sm + OFF_ALO + arow * ROWB + ac8 * 2) = *(const uint4*)lo;
        }
        // ---- load + split W rows: 96 rows (row 0-63 all threads, 64-95 tid<128) ----
        #pragma unroll
        for (int p = 0; p < 2; p++) {
            const int row = arow + p * 64;
            if (p == 0 || tid < 128) {
                const float* wp = W + (size_t)(n0 + row) * K512 + k + ac8;
                const float4 w0 = *(const float4*)(wp);
                const float4 w1 = *(const float4*)(wp + 4);
                const float v[8] = { w0.x, w0.y, w0.z, w0.w, w1.x, w1.y, w1.z, w1.w };
                __align__(16) __nv_bfloat16 hi[8], lo[8];
                #pragma unroll
                for (int i = 0; i < 8; i++) {
                    hi[i] = __float2bfloat16(v[i]);
                    lo[i] = __float2bfloat16(v[i] - __bfloat162float(hi[i]));
                }
                *(uint4*)(sm + OFF_BHI + row * ROWB + ac8 * 2) = *(const uint4*)hi;
                *(uint4*)(sm + OFF_BLO + row * ROWB + ac8 * 2) = *(const uint4*)lo;
            }
        }
        __syncthreads();

        #pragma unroll
        for (int ks = 0; ks < 2; ks++) {
            const int kb = (ks * 16 + c2) * 2;
            uint32_t ah[2][4], al[2][4], bh[3][2], bl[3][2];
            #pragma unroll
            for (int mf = 0; mf < 2; mf++) {
                const char* hb = sm + OFF_AHI + (wm + mf * 16 + r8) * ROWB;
                const char* lb = sm + OFF_ALO + (wm + mf * 16 + r8) * ROWB;
                ah[mf][0] = *(const uint32_t*)(hb + kb);
                ah[mf][1] = *(const uint32_t*)(hb + 8 * ROWB + kb);
                ah[mf][2] = *(const uint32_t*)(hb + kb + 16);
                ah[mf][3] = *(const uint32_t*)(hb + 8 * ROWB + kb + 16);
                al[mf][0] = *(const uint32_t*)(lb + kb);
                al[mf][1] = *(const uint32_t*)(lb + 8 * ROWB + kb);
                al[mf][2] = *(const uint32_t*)(lb + kb + 16);
                al[mf][3] = *(const uint32_t*)(lb + 8 * ROWB + kb + 16);
            }
            #pragma unroll
            for (int nf = 0; nf < 3; nf++) {
                const char* hb = sm + OFF_BHI + (wn + nf * 8 + r8) * ROWB;
                const char* lb = sm + OFF_BLO + (wn + nf * 8 + r8) * ROWB;
                bh[nf][0] = *(const uint32_t*)(hb + kb);
                bh[nf][1] = *(const uint32_t*)(hb + kb + 16);
                bl[nf][0] = *(const uint32_t*)(lb + kb);
                bl[nf][1] = *(const uint32_t*)(lb + kb + 16);
            }
            #pragma unroll
            for (int mf = 0; mf < 2; mf++)
                #pragma unroll
                for (int nf = 0; nf < 3; nf++) {
                    mma16816(acc[mf][nf], ah[mf], bh[nf]);   // hi*hi
                    mma16816(acc[mf][nf], al[mf], bh[nf]);   // lo*hi
                    mma16816(acc[mf][nf], ah[mf], bl[nf]);   // hi*lo
                }
        }
        __syncthreads();
    }

    if (MODE == 0) {
        // plain: acc + bias -> C
        #pragma unroll
        for (int mf = 0; mf < 2; mf++)
            #pragma unroll
            for (int hh = 0; hh < 2; hh++) {
                const int m = m0 + wm + mf * 16 + hh * 8 + r8;
                float* crow = C + (size_t)m * G3 + n0 + wn;
                #pragma unroll
                for (int nf = 0; nf < 3; nf++) {
                    const int n = nf * 8 + c2;
                    float2 v;
                    v.x = acc[mf][nf][hh * 2 + 0] + __ldg(&bias[n0 + wn + n]);
                    v.y = acc[mf][nf][hh * 2 + 1] + __ldg(&bias[n0 + wn + n + 1]);
                    *(float2*)(crow + n) = v;
                }
            }
    } else {
        // stage acc + bias into smem tile S[64][100]
        float* S = (float*)sm;
        #pragma unroll
        for (int mf = 0; mf < 2; mf++)
            #pragma unroll
            for (int hh = 0; hh < 2; hh++) {
                const int m = wm + mf * 16 + hh * 8 + r8;
                #pragma unroll
                for (int nf = 0; nf < 3; nf++) {
                    const int n = wn + nf * 8 + c2;
                    S[m * 100 + n]     = acc[mf][nf][hh * 2 + 0] + __ldg(&bias[n0 + n]);
                    S[m * 100 + n + 1] = acc[mf][nf][hh * 2 + 1] + __ldg(&bias[n0 + n + 1]);
                }
            }
        __syncthreads();

        const int jbase = blockIdx.x * 32;   // n0 / 3
        #pragma unroll
        for (int i = 0; i < 8; i++) {
            const int idx = i * 256 + tid;   // < 2048
            const int m  = idx >> 5;
            const int jj = idx & 31;
            const int mg = m0 + m;
            const float* s = S + m * 100 + 3 * jj;
            const float* o = Gother + (size_t)mg * G3 + n0 + 3 * jj;
            float r, z, nn;
            if (MODE == 1) {                 // s = GH triple, o = GI triple
                r  = sigmoidf_(o[0] + s[0]);
                z  = sigmoidf_(o[1] + s[1]);
                nn = tanhf    (o[2] + r * s[2]);
            } else {                         // s = GI triple, o = GH triple
                r  = sigmoidf_(s[0] + o[0]);
                z  = sigmoidf_(s[1] + o[1]);
                nn = tanhf    (s[2] + r * o[2]);
            }
            const size_t hidx = (size_t)mg * H + jbase + jj;
            const float hv = (1.0f - z) * nn + z * hold[hidx];
            hout[hidx] = hv;
            if (MODE == 2) h2a[hidx] = hv;
        }
    }
}

// ---- kernels ----
__global__ void __launch_bounds__(256) k_gi1(const float* __restrict__ x,
                                             const float* __restrict__ bias) {
    gemm96<0>(x + blockIdx.z, XW, g_Wih1p, bias,
              g_GI1 + (size_t)blockIdx.z * B * G3, nullptr, nullptr, nullptr, nullptr);
}
// Launch A: z=0 GH1+gate1 fused; z=1 GH2 plain.
__global__ void __launch_bounds__(256) k_stepA(int t, int cur) {
    if (blockIdx.z == 0)
        gemm96<1>(g_h1x[cur], H, g_Whh1p, g_bhh1p, nullptr,
                  g_GI1 + (size_t)t * B * G3, g_h1x[cur], g_h1x[cur ^ 1], nullptr);
    else
        gemm96<0>(g_h2x[cur], H, g_Whh2p, g_bhh2p, g_GH2, nullptr, nullptr, nullptr, nullptr);
}
// Launch B: GI2+gate2 fused.
__global__ void __launch_bounds__(256) k_stepB(int t, int cur) {
    gemm96<2>(g_h1x[cur ^ 1], H, g_Wih2p, g_bih2p, nullptr,
              g_GH2, g_h2x[cur], g_h2x[cur ^ 1],
              g_H2A + (size_t)t * B * H);
}

// ---- prep: permute weights/biases to gate-interleaved row order ----
__global__ void k_perm(const float* __restrict__ src, float* __restrict__ dst) {
    const int idx = blockIdx.x * blockDim.x + threadIdx.x;   // < G3*K512
    const int row = idx >> 9;          // g*512 + j
    const int k   = idx & 511;
    const int g = row >> 9, j = row & 511;
    dst[(size_t)(3 * j + g) * K512 + k] = src[idx];
}
__global__ void k_permb(const float* __restrict__ b1, float* __restrict__ d1,
                        const float* __restrict__ b2, float* __restrict__ d2,
                        const float* __restrict__ b3, float* __restrict__ d3,
                        const float* __restrict__ b4, float* __restrict__ d4) {
    const int idx = blockIdx.x * blockDim.x + threadIdx.x;   // < G3
    const int g = idx >> 9, j = idx & 511;
    const int p = 3 * j + g;
    d1[p] = b1[idx]; d2[p] = b2[idx]; d3[p] = b3[idx]; d4[p] = b4[idx];
}
__global__ void k_init(const float* __restrict__ h1i, const float* __restrict__ h2i) {
    const int i = blockIdx.x * blockDim.x + threadIdx.x;
    g_h1x[0][i] = h1i[i];
    g_h2x[0][i] = h2i[i];
}

// ---- FC head + finalize ----
__global__ void k_y(const float* __restrict__ Wfc, const float* __restrict__ bfc,
                    float* __restrict__ out) {
    const int w    = (blockIdx.x * blockDim.x + threadIdx.x) >> 5;
    const int lane = threadIdx.x & 31;
    const int b = w >> 6;
    const int t = w & (L - 1);
    const float* h2 = g_H2A + ((size_t)t * B + b) * H;
    float acc = 0.0f;
    #pragma unroll 4
    for (int j = lane; j < H; j += 32) acc += h2[j] * Wfc[j];
    #pragma unroll
    for (int o = 16; o; o >>= 1) acc += __shfl_xor_sync(0xffffffffu, acc, o);
    if (lane == 0) out[b * L + t] = acc + bfc[0];
}
__global__ void k_fin(float* __restrict__ out) {
    const int i = blockIdx.x * blockDim.x + threadIdx.x;
    out[B * L + i]         = g_h1x[0][i];   // L=64 even -> final state in buf 0
    out[B * L + B * H + i] = g_h2x[0][i];
}

// ---------------------------------------------------------------
extern "C" void kernel_launch(void* const* d_in, const int* in_sizes, int n_in,
                              void* d_out, int out_size)
{
    (void)in_sizes; (void)n_in; (void)out_size;
    const float* x    = (const float*)d_in[0];
    const float* h1i  = (const float*)d_in[1];
    const float* h2i  = (const float*)d_in[2];
    const float* Wih1 = (const float*)d_in[3];
    const float* Whh1 = (const float*)d_in[4];
    const float* bih1 = (const float*)d_in[5];
    const float* bhh1 = (const float*)d_in[6];
    const float* Wih2 = (const float*)d_in[7];
    const float* Whh2 = (const float*)d_in[8];
    const float* bih2 = (const float*)d_in[9];
    const float* bhh2 = (const float*)d_in[10];
    const float* Wfc  = (const float*)d_in[11];
    const float* bfc  = (const float*)d_in[12];
    float* out = (float*)d_out;

    // prep
    const int PW = (G3 * K512) / 256;
    float* d_bih1p; cudaGetSymbolAddress((void**)&d_bih1p, g_bih1p);
    float* d_bhh1p; cudaGetSymbolAddress((void**)&d_bhh1p, g_bhh1p);
    float* d_bih2p; cudaGetSymbolAddress((void**)&d_bih2p, g_bih2p);
    float* d_bhh2p; cudaGetSymbolAddress((void**)&d_bhh2p, g_bhh2p);
    float* d_Wih1p; cudaGetSymbolAddress((void**)&d_Wih1p, g_Wih1p);
    float* d_Whh1p; cudaGetSymbolAddress((void**)&d_Whh1p, g_Whh1p);
    float* d_Wih2p; cudaGetSymbolAddress((void**)&d_Wih2p, g_Wih2p);
    float* d_Whh2p; cudaGetSymbolAddress((void**)&d_Whh2p, g_Whh2p);
    k_perm<<<PW, 256>>>(Wih1, d_Wih1p);
    k_perm<<<PW, 256>>>(Whh1, d_Whh1p);
    k_perm<<<PW, 256>>>(Wih2, d_Wih2p);
    k_perm<<<PW, 256>>>(Whh2, d_Whh2p);
    k_permb<<<G3 / 256, 256>>>(bih1, d_bih1p, bhh1, d_bhh1p,
                               bih2, d_bih2p, bhh2, d_bhh2p);
    k_init<<<(B * H) / 256, 256>>>(h1i, h2i);

    // Hoisted input-side GEMM for all L steps (permuted output).
    k_gi1<<<dim3(G3 / TN, B / TM, L), 256, SMEM_DYN>>>(x, d_bih1p);

    for (int t = 0; t < L; t++) {
        const int cur = t & 1;
        k_stepA<<<dim3(G3 / TN, B / TM, 2), 256, SMEM_DYN>>>(t, cur);
        k_stepB<<<dim3(G3 / TN, B / TM, 1), 256, SMEM_DYN>>>(t, cur);
    }

    k_y  <<<(B * L * 32) / 256, 256>>>(Wfc, bfc, out);
    k_fin<<<(B * H) / 256, 256>>>(out);
}

// round 11
// speedup vs baseline: 1.2979x; 1.2979x over previous
#include <cuda_runtime.h>
#include <cuda_bf16.h>
#include <math.h>
#include <stdint.h>

// Problem dims
#define B   512
#define T   512
#define L   64
#define H   512
#define G3  1536
#define XW  575
#define K512 512
#define BK   32
#define NIT  16           // K512 / BK
#define TM   64
#define TN   96           // 32 gate-triples per tile
#define NCTA 128          // persistent grid (<= SM count, all co-resident)
#define ROWB 80
#define OFF_AHI 0
#define OFF_ALO 5120
#define OFF_BHI 10240
#define OFF_BLO 17920
#define SMEM_DYN 25600

// -------- device scratch --------
__device__ float g_GI1[(size_t)L * B * G3];    // permuted x-side gates, layer 1
__device__ float g_GH2[(size_t)B * G3];        // permuted h-side gates, layer 2
__device__ float g_h1x[2][(size_t)B * H];
__device__ float g_h2x[2][(size_t)B * H];
__device__ float g_H2A[(size_t)L * B * H];
__device__ __align__(16) float g_Wih1p[(size_t)G3 * K512];
__device__ __align__(16) float g_Whh1p[(size_t)G3 * K512];
__device__ __align__(16) float g_Wih2p[(size_t)G3 * K512];
__device__ __align__(16) float g_Whh2p[(size_t)G3 * K512];
__device__ float g_bih1p[G3], g_bhh1p[G3], g_bih2p[G3], g_bhh2p[G3];
__device__ unsigned g_barcnt;                  // persistent-kernel barrier counter

// ---------------- helpers ----------------
__device__ __forceinline__ void mma16816(float* d, const uint32_t* a, const uint32_t* b) {
    asm volatile(
        "mma.sync.aligned.m16n8k16.row.col.f32.bf16.bf16.f32 "
        "{%0,%1,%2,%3}, {%4,%5,%6,%7}, {%8,%9}, {%0,%1,%2,%3};"
        : "+f"(d[0]), "+f"(d[1]), "+f"(d[2]), "+f"(d[3])
        : "r"(a[0]), "r"(a[1]), "r"(a[2]), "r"(a[3]), "r"(b[0]), "r"(b[1]));
}
__device__ __forceinline__ float sigmoidf_(float v) { return 1.0f / (1.0f + expf(-v)); }

// Grid barrier: release-add then acquire-spin. All NCTA CTAs co-resident.
__device__ __forceinline__ void gbar(unsigned& target) {
    __syncthreads();
    if (threadIdx.x == 0) {
        target += NCTA;
        __threadfence();
        atomicAdd(&g_barcnt, 1u);
        unsigned v;
        do {
            asm volatile("ld.acquire.gpu.u32 %0, [%1];"
                         : "=r"(v) : "l"(&g_barcnt) : "memory");
        } while (v < target);
    }
    __syncthreads();
}

// ---------------------------------------------------------------
// 64x96 tile GEMM with in-smem fp32->(hi,lo) bf16 split and 3-term
// compensated mma (validated rounds 7-8). CG=true: mutable operands
// read via __ldcg (L2-only) for cross-barrier visibility.
// MODE 0: C tile -> gmem. MODE 1: fused gate1. MODE 2: fused gate2.
// ---------------------------------------------------------------
template<int MODE, bool CG>
__device__ void gemm96p(int bx, int by,
                        const float* __restrict__ A, int lda,
                        const float* __restrict__ W,
                        const float* __restrict__ bias,
                        float* __restrict__ C,
                        const float* __restrict__ Gother,
                        const float* __restrict__ hold,
                        float* __restrict__ hout,
                        float* __restrict__ h2a)
{
    extern __shared__ __align__(128) char sm[];
    const int tid  = threadIdx.x;
    const int wid  = tid >> 5;
    const int lane = tid & 31;
    const int m0 = by * TM;
    const int n0 = bx * TN;

    const int arow = tid >> 2;
    const int ac8  = (tid & 3) * 8;

    const int wm = (wid & 1) * 32;
    const int wn = (wid >> 1) * 24;
    const int r8 = lane >> 2;
    const int c2 = (lane & 3) * 2;

    float acc[2][3][4] = {};

    for (int it = 0; it < NIT; it++) {
        const int k = it * BK;
        {
            const float* ap = A + (size_t)(m0 + arow) * lda + k + ac8;
            __align__(16) __nv_bfloat16 hi[8], lo[8];
            #pragma unroll
            for (int i = 0; i < 8; i++) {
                const float v = CG ? __ldcg(ap + i) : ap[i];
                hi[i] = __float2bfloat16(v);
                lo[i] = __float2bfloat16(v - __bfloat162float(hi[i]));
            }
            *(uint4*)(sm + OFF_AHI + arow * ROWB + ac8 * 2) = *(const uint4*)hi;
            *(uint4*)(sm + OFF_ALO + arow * ROWB + ac8 * 2) = *(const uint4*)lo;
        }
        #pragma unroll
        for (int p = 0; p < 2; p++) {
            const int row = arow + p * 64;
            if (p == 0 || tid < 128) {
                const float* wp = W + (size_t)(n0 + row) * K512 + k + ac8;
                const float4 w0 = *(const float4*)(wp);
                const float4 w1 = *(const float4*)(wp + 4);
                const float v[8] = { w0.x, w0.y, w0.z, w0.w, w1.x, w1.y, w1.z, w1.w };
                __align__(16) __nv_bfloat16 hi[8], lo[8];
                #pragma unroll
                for (int i = 0; i < 8; i++) {
                    hi[i] = __float2bfloat16(v[i]);
                    lo[i] = __float2bfloat16(v[i] - __bfloat162float(hi[i]));
                }
                *(uint4*)(sm + OFF_BHI + row * ROWB + ac8 * 2) = *(const uint4*)hi;
                *(uint4*)(sm + OFF_BLO + row * ROWB + ac8 * 2) = *(const uint4*)lo;
            }
        }
        __syncthreads();

        #pragma unroll
        for (int ks = 0; ks < 2; ks++) {
            const int kb = (ks * 16 + c2) * 2;
            uint32_t ah[2][4], al[2][4], bh[3][2], bl[3][2];
            #pragma unroll
            for (int mf = 0; mf < 2; mf++) {
                const char* hb = sm + OFF_AHI + (wm + mf * 16 + r8) * ROWB;
                const char* lb = sm + OFF_ALO + (wm + mf * 16 + r8) * ROWB;
                ah[mf][0] = *(const uint32_t*)(hb + kb);
                ah[mf][1] = *(const uint32_t*)(hb + 8 * ROWB + kb);
                ah[mf][2] = *(const uint32_t*)(hb + kb + 16);
                ah[mf][3] = *(const uint32_t*)(hb + 8 * ROWB + kb + 16);
                al[mf][0] = *(const uint32_t*)(lb + kb);
                al[mf][1] = *(const uint32_t*)(lb + 8 * ROWB + kb);
                al[mf][2] = *(const uint32_t*)(lb + kb + 16);
                al[mf][3] = *(const uint32_t*)(lb + 8 * ROWB + kb + 16);
            }
            #pragma unroll
            for (int nf = 0; nf < 3; nf++) {
                const char* hb = sm + OFF_BHI + (wn + nf * 8 + r8) * ROWB;
                const char* lb = sm + OFF_BLO + (wn + nf * 8 + r8) * ROWB;
                bh[nf][0] = *(const uint32_t*)(hb + kb);
                bh[nf][1] = *(const uint32_t*)(hb + kb + 16);
                bl[nf][0] = *(const uint32_t*)(lb + kb);
                bl[nf][1] = *(const uint32_t*)(lb + kb + 16);
            }
            #pragma unroll
            for (int mf = 0; mf < 2; mf++)
                #pragma unroll
                for (int nf = 0; nf < 3; nf++) {
                    mma16816(acc[mf][nf], ah[mf], bh[nf]);
                    mma16816(acc[mf][nf], al[mf], bh[nf]);
                    mma16816(acc[mf][nf], ah[mf], bl[nf]);
                }
        }
        __syncthreads();
    }

    if (MODE == 0) {
        #pragma unroll
        for (int mf = 0; mf < 2; mf++)
            #pragma unroll
            for (int hh = 0; hh < 2; hh++) {
                const int m = m0 + wm + mf * 16 + hh * 8 + r8;
                float* crow = C + (size_t)m * G3 + n0 + wn;
                #pragma unroll
                for (int nf = 0; nf < 3; nf++) {
                    const int n = nf * 8 + c2;
                    float2 v;
                    v.x = acc[mf][nf][hh * 2 + 0] + __ldg(&bias[n0 + wn + n]);
                    v.y = acc[mf][nf][hh * 2 + 1] + __ldg(&bias[n0 + wn + n + 1]);
                    *(float2*)(crow + n) = v;
                }
            }
    } else {
        float* S = (float*)sm;
        #pragma unroll
        for (int mf = 0; mf < 2; mf++)
            #pragma unroll
            for (int hh = 0; hh < 2; hh++) {
                const int m = wm + mf * 16 + hh * 8 + r8;
                #pragma unroll
                for (int nf = 0; nf < 3; nf++) {
                    const int n = wn + nf * 8 + c2;
                    S[m * 100 + n]     = acc[mf][nf][hh * 2 + 0] + __ldg(&bias[n0 + n]);
                    S[m * 100 + n + 1] = acc[mf][nf][hh * 2 + 1] + __ldg(&bias[n0 + n + 1]);
                }
            }
        __syncthreads();

        const int jbase = bx * 32;
        #pragma unroll
        for (int i = 0; i < 8; i++) {
            const int idx = i * 256 + tid;
            const int m  = idx >> 5;
            const int jj = idx & 31;
            const int mg = m0 + m;
            const float* s = S + m * 100 + 3 * jj;
            const float* o = Gother + (size_t)mg * G3 + n0 + 3 * jj;
            float o0, o1, o2;
            if (CG && MODE == 2) { o0 = __ldcg(o); o1 = __ldcg(o + 1); o2 = __ldcg(o + 2); }
            else                 { o0 = o[0];      o1 = o[1];          o2 = o[2]; }
            float r, z, nn;
            if (MODE == 1) {
                r  = sigmoidf_(o0 + s[0]);
                z  = sigmoidf_(o1 + s[1]);
                nn = tanhf    (o2 + r * s[2]);
            } else {
                r  = sigmoidf_(s[0] + o0);
                z  = sigmoidf_(s[1] + o1);
                nn = tanhf    (s[2] + r * o2);
            }
            const size_t hidx = (size_t)mg * H + jbase + jj;
            const float hprev = CG ? __ldcg(hold + hidx) : hold[hidx];
            const float hv = (1.0f - z) * nn + z * hprev;
            hout[hidx] = hv;
            if (MODE == 2) h2a[hidx] = hv;
        }
    }
    __syncthreads();   // smem reuse safety for back-to-back tiles
}

// ---- hoisted input-side GEMM (separate kernel, classic grid) ----
__global__ void __launch_bounds__(256) k_gi1(const float* __restrict__ x,
                                             const float* __restrict__ bias) {
    gemm96p<0, false>(blockIdx.x, blockIdx.y, x + blockIdx.z, XW, g_Wih1p, bias,
                      g_GI1 + (size_t)blockIdx.z * B * G3,
                      nullptr, nullptr, nullptr, nullptr);
}

// ---- persistent recurrent loop: all 64 steps, 2 grid barriers/step ----
__global__ void __launch_bounds__(256, 1) k_loop()
{
    unsigned bar_target = 0;
    const int bx = blockIdx.x & 15;
    const int by = blockIdx.x >> 4;

    for (int t = 0; t < L; t++) {
        const int cur = t & 1;
        const int nxt = cur ^ 1;

        // Phase A, tile 1: GH1 + fused gate1 -> h1[nxt]
        gemm96p<1, true>(bx, by, g_h1x[cur], H, g_Whh1p, g_bhh1p, nullptr,
                         g_GI1 + (size_t)t * B * G3, g_h1x[cur], g_h1x[nxt], nullptr);
        // Phase A, tile 2: GH2 -> g_GH2
        gemm96p<0, true>(bx, by, g_h2x[cur], H, g_Whh2p, g_bhh2p, g_GH2,
                         nullptr, nullptr, nullptr, nullptr);
        gbar(bar_target);

        // Phase B: GI2 + fused gate2 -> h2[nxt] (+H2A log)
        gemm96p<2, true>(bx, by, g_h1x[nxt], H, g_Wih2p, g_bih2p, nullptr,
                         g_GH2, g_h2x[cur], g_h2x[nxt],
                         g_H2A + (size_t)t * B * H);
        gbar(bar_target);
    }
}

// ---- prep ----
__global__ void k_perm(const float* __restrict__ src, float* __restrict__ dst) {
    const int idx = blockIdx.x * blockDim.x + threadIdx.x;
    const int row = idx >> 9;
    const int k   = idx & 511;
    const int g = row >> 9, j = row & 511;
    dst[(size_t)(3 * j + g) * K512 + k] = src[idx];
}
__global__ void k_permb(const float* __restrict__ b1, float* __restrict__ d1,
                        const float* __restrict__ b2, float* __restrict__ d2,
                        const float* __restrict__ b3, float* __restrict__ d3,
                        const float* __restrict__ b4, float* __restrict__ d4) {
    const int idx = blockIdx.x * blockDim.x + threadIdx.x;
    const int g = idx >> 9, j = idx & 511;
    const int p = 3 * j + g;
    d1[p] = b1[idx]; d2[p] = b2[idx]; d3[p] = b3[idx]; d4[p] = b4[idx];
}
__global__ void k_init(const float* __restrict__ h1i, const float* __restrict__ h2i) {
    const int i = blockIdx.x * blockDim.x + threadIdx.x;
    g_h1x[0][i] = h1i[i];
    g_h2x[0][i] = h2i[i];
    if (i == 0) g_barcnt = 0;          // reset persistent barrier each launch
}

// ---- FC head + finalize ----
__global__ void k_y(const float* __restrict__ Wfc, const float* __restrict__ bfc,
                    float* __restrict__ out) {
    const int w    = (blockIdx.x * blockDim.x + threadIdx.x) >> 5;
    const int lane = threadIdx.x & 31;
    const int b = w >> 6;
    const int t = w & (L - 1);
    const float* h2 = g_H2A + ((size_t)t * B + b) * H;
    float acc = 0.0f;
    #pragma unroll 4
    for (int j = lane; j < H; j += 32) acc += h2[j] * Wfc[j];
    #pragma unroll
    for (int o = 16; o; o >>= 1) acc += __shfl_xor_sync(0xffffffffu, acc, o);
    if (lane == 0) out[b * L + t] = acc + bfc[0];
}
__global__ void k_fin(float* __restrict__ out) {
    const int i = blockIdx.x * blockDim.x + threadIdx.x;
    out[B * L + i]         = g_h1x[0][i];   // L even -> final state in buf 0
    out[B * L + B * H + i] = g_h2x[0][i];
}

// ---------------------------------------------------------------
extern "C" void kernel_launch(void* const* d_in, const int* in_sizes, int n_in,
                              void* d_out, int out_size)
{
    (void)in_sizes; (void)n_in; (void)out_size;
    const float* x    = (const float*)d_in[0];
    const float* h1i  = (const float*)d_in[1];
    const float* h2i  = (const float*)d_in[2];
    const float* Wih1 = (const float*)d_in[3];
    const float* Whh1 = (const float*)d_in[4];
    const float* bih1 = (const float*)d_in[5];
    const float* bhh1 = (const float*)d_in[6];
    const float* Wih2 = (const float*)d_in[7];
    const float* Whh2 = (const float*)d_in[8];
    const float* bih2 = (const float*)d_in[9];
    const float* bhh2 = (const float*)d_in[10];
    const float* Wfc  = (const float*)d_in[11];
    const float* bfc  = (const float*)d_in[12];
    float* out = (float*)d_out;

    const int PW = (G3 * K512) / 256;
    float* d_bih1p; cudaGetSymbolAddress((void**)&d_bih1p, g_bih1p);
    float* d_Wih1p; cudaGetSymbolAddress((void**)&d_Wih1p, g_Wih1p);
    float* d_Whh1p; cudaGetSymbolAddress((void**)&d_Whh1p, g_Whh1p);
    float* d_Wih2p; cudaGetSymbolAddress((void**)&d_Wih2p, g_Wih2p);
    float* d_Whh2p; cudaGetSymbolAddress((void**)&d_Whh2p, g_Whh2p);
    float* d_bhh1p; cudaGetSymbolAddress((void**)&d_bhh1p, g_bhh1p);
    float* d_bih2p; cudaGetSymbolAddress((void**)&d_bih2p, g_bih2p);
    float* d_bhh2p; cudaGetSymbolAddress((void**)&d_bhh2p, g_bhh2p);
    k_perm<<<PW, 256>>>(Wih1, d_Wih1p);
    k_perm<<<PW, 256>>>(Whh1, d_Whh1p);
    k_perm<<<PW, 256>>>(Wih2, d_Wih2p);
    k_perm<<<PW, 256>>>(Whh2, d_Whh2p);
    k_permb<<<G3 / 256, 256>>>(bih1, d_bih1p, bhh1, d_bhh1p,
                               bih2, d_bih2p, bhh2, d_bhh2p);
    k_init<<<(B * H) / 256, 256>>>(h1i, h2i);

    // Hoisted input-side GEMM for all L steps (permuted N layout).
    k_gi1<<<dim3(G3 / TN, B / TM, L), 256, SMEM_DYN>>>(x, d_bih1p);

    // Entire recurrence in ONE persistent kernel.
    k_loop<<<NCTA, 256, SMEM_DYN>>>();

    k_y  <<<(B * L * 32) / 256, 256>>>(Wfc, bfc, out);
    k_fin<<<(B * H) / 256, 256>>>(out);
}

// round 14
// speedup vs baseline: 1.4943x; 1.1514x over previous
#include <cuda_runtime.h>
#include <cuda_bf16.h>
#include <math.h>
#include <stdint.h>

// Problem dims
#define B   512
#define T   512
#define L   64
#define H   512
#define G3  1536
#define XW  575
#define K512 512
#define BK   32
#define NIT  16           // K512 / BK
#define TM   64
#define TN   96           // 32 gate-triples per tile
#define NCTA 128          // persistent grid (all co-resident)
#define ROWB 80
#define OFF_AHI 0
#define OFF_ALO 5120
#define OFF_BHI 10240
#define OFF_BLO 17920
#define SMEM_DYN 25600

// -------- device scratch --------
__device__ float g_GI1[(size_t)L * B * G3];    // permuted x-side gates, layer 1
__device__ float g_GH2[(size_t)B * G3];        // permuted h-side gates, layer 2
__device__ float g_h1x[2][(size_t)B * H];
__device__ float g_h2x[2][(size_t)B * H];
__device__ float g_H2A[(size_t)L * B * H];
// permuted (row' = 3j+gate) pre-split bf16 weights
__device__ __align__(16) __nv_bfloat16 g_Wih1h[(size_t)G3 * K512], g_Wih1l[(size_t)G3 * K512];
__device__ __align__(16) __nv_bfloat16 g_Whh1h[(size_t)G3 * K512], g_Whh1l[(size_t)G3 * K512];
__device__ __align__(16) __nv_bfloat16 g_Wih2h[(size_t)G3 * K512], g_Wih2l[(size_t)G3 * K512];
__device__ __align__(16) __nv_bfloat16 g_Whh2h[(size_t)G3 * K512], g_Whh2l[(size_t)G3 * K512];
__device__ float g_bih1p[G3], g_bhh1p[G3], g_bih2p[G3], g_bhh2p[G3];
__device__ unsigned g_barcnt;

// ---------------- helpers ----------------
__device__ __forceinline__ void mma16816(float* d, const uint32_t* a, const uint32_t* b) {
    asm volatile(
        "mma.sync.aligned.m16n8k16.row.col.f32.bf16.bf16.f32 "
        "{%0,%1,%2,%3}, {%4,%5,%6,%7}, {%8,%9}, {%0,%1,%2,%3};"
        : "+f"(d[0]), "+f"(d[1]), "+f"(d[2]), "+f"(d[3])
        : "r"(a[0]), "r"(a[1]), "r"(a[2]), "r"(a[3]), "r"(b[0]), "r"(b[1]));
}
__device__ __forceinline__ float sigmoidf_(float v) { return 1.0f / (1.0f + expf(-v)); }

// Grid barrier: release-add then acquire-spin (validated round 11).
__device__ __forceinline__ void gbar(unsigned& target) {
    __syncthreads();
    if (threadIdx.x == 0) {
        target += NCTA;
        __threadfence();
        atomicAdd(&g_barcnt, 1u);
        unsigned v;
        do {
            asm volatile("ld.acquire.gpu.u32 %0, [%1];"
                         : "=r"(v) : "l"(&g_barcnt) : "memory");
        } while (v < target);
    }
    __syncthreads();
}

// ---------------------------------------------------------------
// 64x96 tile GEMM, 3-term compensated split-bf16 mma (validated R7-R11).
// NEW: weights arrive pre-split bf16 (hi/lo), register-double-buffered
// prefetch hides global latency behind the mma phase.
// MODE 0: C tile -> gmem. MODE 1: fused gate1. MODE 2: fused gate2.
// ---------------------------------------------------------------
template<int MODE, bool CG>
__device__ void gemm96p(int bx, int by,
                        const float* __restrict__ A, int lda,
                        const __nv_bfloat16* __restrict__ Wh,
                        const __nv_bfloat16* __restrict__ Wl,
                        const float* __restrict__ bias,
                        float* __restrict__ C,
                        const float* __restrict__ Gother,
                        const float* __restrict__ hold,
                        float* __restrict__ hout,
                        float* __restrict__ h2a)
{
    extern __shared__ __align__(128) char sm[];
    const int tid  = threadIdx.x;
    const int wid  = tid >> 5;
    const int lane = tid & 31;
    const int m0 = by * TM;
    const int n0 = bx * TN;

    const int arow = tid >> 2;          // 0..63
    const int ac8  = (tid & 3) * 8;     // 8-float group in BK=32

    const int wm = (wid & 1) * 32;
    const int wn = (wid >> 1) * 24;
    const int r8 = lane >> 2;
    const int c2 = (lane & 3) * 2;

    float acc[2][3][4] = {};

    float pa[8];                        // prefetched A (fp32)
    uint4 pwh[2], pwl[2];               // prefetched W hi/lo (8 bf16 each)

    #define PREFETCH(itv) do {                                                    \
        const int _k = (itv) * BK;                                                \
        const float* _ap = A + (size_t)(m0 + arow) * lda + _k + ac8;              \
        _Pragma("unroll")                                                         \
        for (int i = 0; i < 8; i++) pa[i] = CG ? __ldcg(_ap + i) : _ap[i];        \
        {                                                                         \
            const size_t _o0 = (size_t)(n0 + arow) * K512 + _k + ac8;             \
            pwh[0] = *(const uint4*)(Wh + _o0);                                   \
            pwl[0] = *(const uint4*)(Wl + _o0);                                   \
        }                                                                         \
        if (tid < 128) {                                                          \
            const size_t _o1 = (size_t)(n0 + arow + 64) * K512 + _k + ac8;        \
            pwh[1] = *(const uint4*)(Wh + _o1);                                   \
            pwl[1] = *(const uint4*)(Wl + _o1);                                   \
        }                                                                         \
    } while (0)

    #define STORE_SM() do {                                                       \
        __align__(16) __nv_bfloat16 _hi[8], _lo[8];                               \
        _Pragma("unroll")                                                         \
        for (int i = 0; i < 8; i++) {                                             \
            _hi[i] = __float2bfloat16(pa[i]);                                     \
            _lo[i] = __float2bfloat16(pa[i] - __bfloat162float(_hi[i]));          \
        }                                                                         \
        *(uint4*)(sm + OFF_AHI + arow * ROWB + ac8 * 2) = *(const uint4*)_hi;     \
        *(uint4*)(sm + OFF_ALO + arow * ROWB + ac8 * 2) = *(const uint4*)_lo;     \
        *(uint4*)(sm + OFF_BHI + arow * ROWB + ac8 * 2) = pwh[0];                 \
        *(uint4*)(sm + OFF_BLO + arow * ROWB + ac8 * 2) = pwl[0];                 \
        if (tid < 128) {                                                          \
            *(uint4*)(sm + OFF_BHI + (arow + 64) * ROWB + ac8 * 2) = pwh[1];      \
            *(uint4*)(sm + OFF_BLO + (arow + 64) * ROWB + ac8 * 2) = pwl[1];      \
        }                                                                         \
    } while (0)

    PREFETCH(0);

    for (int it = 0; it < NIT; it++) {
        STORE_SM();
        __syncthreads();
        if (it + 1 < NIT) PREFETCH(it + 1);   // overlaps mma below

        #pragma unroll
        for (int ks = 0; ks < 2; ks++) {
            const int kb = (ks * 16 + c2) * 2;
            uint32_t ah[2][4], al[2][4], bh[3][2], bl[3][2];
            #pragma unroll
            for (int mf = 0; mf < 2; mf++) {
                const char* hb = sm + OFF_AHI + (wm + mf * 16 + r8) * ROWB;
                const char* lb = sm + OFF_ALO + (wm + mf * 16 + r8) * ROWB;
                ah[mf][0] = *(const uint32_t*)(hb + kb);
                ah[mf][1] = *(const uint32_t*)(hb + 8 * ROWB + kb);
                ah[mf][2] = *(const uint32_t*)(hb + kb + 16);
                ah[mf][3] = *(const uint32_t*)(hb + 8 * ROWB + kb + 16);
                al[mf][0] = *(const uint32_t*)(lb + kb);
                al[mf][1] = *(const uint32_t*)(lb + 8 * ROWB + kb);
                al[mf][2] = *(const uint32_t*)(lb + kb + 16);
                al[mf][3] = *(const uint32_t*)(lb + 8 * ROWB + kb + 16);
            }
            #pragma unroll
            for (int nf = 0; nf < 3; nf++) {
                const char* hb = sm + OFF_BHI + (wn + nf * 8 + r8) * ROWB;
                const char* lb = sm + OFF_BLO + (wn + nf * 8 + r8) * ROWB;
                bh[nf][0] = *(const uint32_t*)(hb + kb);
                bh[nf][1] = *(const uint32_t*)(hb + kb + 16);
                bl[nf][0] = *(const uint32_t*)(lb + kb);
                bl[nf][1] = *(const uint32_t*)(lb + kb + 16);
            }
            #pragma unroll
            for (int mf = 0; mf < 2; mf++)
                #pragma unroll
                for (int nf = 0; nf < 3; nf++) {
                    mma16816(acc[mf][nf], ah[mf], bh[nf]);
                    mma16816(acc[mf][nf], al[mf], bh[nf]);
                    mma16816(acc[mf][nf], ah[mf], bl[nf]);
                }
        }
        __syncthreads();
    }
    #undef PREFETCH
    #undef STORE_SM

    if (MODE == 0) {
        #pragma unroll
        for (int mf = 0; mf < 2; mf++)
            #pragma unroll
            for (int hh = 0; hh < 2; hh++) {
                const int m = m0 + wm + mf * 16 + hh * 8 + r8;
                float* crow = C + (size_t)m * G3 + n0 + wn;
                #pragma unroll
                for (int nf = 0; nf < 3; nf++) {
                    const int n = nf * 8 + c2;
                    float2 v;
                    v.x = acc[mf][nf][hh * 2 + 0] + __ldg(&bias[n0 + wn + n]);
                    v.y = acc[mf][nf][hh * 2 + 1] + __ldg(&bias[n0 + wn + n + 1]);
                    *(float2*)(crow + n) = v;
                }
            }
    } else {
        float* S = (float*)sm;
        #pragma unroll
        for (int mf = 0; mf < 2; mf++)
            #pragma unroll
            for (int hh = 0; hh < 2; hh++) {
                const int m = wm + mf * 16 + hh * 8 + r8;
                #pragma unroll
                for (int nf = 0; nf < 3; nf++) {
                    const int n = wn + nf * 8 + c2;
                    S[m * 100 + n]     = acc[mf][nf][hh * 2 + 0] + __ldg(&bias[n0 + n]);
                    S[m * 100 + n + 1] = acc[mf][nf][hh * 2 + 1] + __ldg(&bias[n0 + n + 1]);
                }
            }
        __syncthreads();

        const int jbase = bx * 32;
        #pragma unroll
        for (int i = 0; i < 8; i++) {
            const int idx = i * 256 + tid;
            const int m  = idx >> 5;
            const int jj = idx & 31;
            const int mg = m0 + m;
            const float* s = S + m * 100 + 3 * jj;
            const float* o = Gother + (size_t)mg * G3 + n0 + 3 * jj;
            float o0, o1, o2;
            if (CG && MODE == 2) { o0 = __ldcg(o); o1 = __ldcg(o + 1); o2 = __ldcg(o + 2); }
            else                 { o0 = o[0];      o1 = o[1];          o2 = o[2]; }
            float r, z, nn;
            if (MODE == 1) {
                r  = sigmoidf_(o0 + s[0]);
                z  = sigmoidf_(o1 + s[1]);
                nn = tanhf    (o2 + r * s[2]);
            } else {
                r  = sigmoidf_(s[0] + o0);
                z  = sigmoidf_(s[1] + o1);
                nn = tanhf    (s[2] + r * o2);
            }
            const size_t hidx = (size_t)mg * H + jbase + jj;
            const float hprev = CG ? __ldcg(hold + hidx) : hold[hidx];
            const float hv = (1.0f - z) * nn + z * hprev;
            hout[hidx] = hv;
            if (MODE == 2) h2a[hidx] = hv;
        }
    }
    __syncthreads();
}

// ---- hoisted input-side GEMM ----
__global__ void __launch_bounds__(256) k_gi1(const float* __restrict__ x,
                                             const float* __restrict__ bias) {
    gemm96p<0, false>(blockIdx.x, blockIdx.y, x + blockIdx.z, XW,
                      g_Wih1h, g_Wih1l, bias,
                      g_GI1 + (size_t)blockIdx.z * B * G3,
                      nullptr, nullptr, nullptr, nullptr);
}

// ---- persistent recurrent loop ----
__global__ void __launch_bounds__(256, 1) k_loop()
{
    unsigned bar_target = 0;
    const int bx = blockIdx.x & 15;
    const int by = blockIdx.x >> 4;

    for (int t = 0; t < L; t++) {
        const int cur = t & 1;
        const int nxt = cur ^ 1;

        gemm96p<1, true>(bx, by, g_h1x[cur], H, g_Whh1h, g_Whh1l, g_bhh1p, nullptr,
                         g_GI1 + (size_t)t * B * G3, g_h1x[cur], g_h1x[nxt], nullptr);
        gemm96p<0, true>(bx, by, g_h2x[cur], H, g_Whh2h, g_Whh2l, g_bhh2p, g_GH2,
                         nullptr, nullptr, nullptr, nullptr);
        gbar(bar_target);

        gemm96p<2, true>(bx, by, g_h1x[nxt], H, g_Wih2h, g_Wih2l, g_bih2p, nullptr,
                         g_GH2, g_h2x[cur], g_h2x[nxt],
                         g_H2A + (size_t)t * B * H);
        gbar(bar_target);
    }
}

// ---- prep: permute + pre-split weights to bf16 hi/lo ----
__global__ void k_perm(const float* __restrict__ src,
                       __nv_bfloat16* __restrict__ dh,
                       __nv_bfloat16* __restrict__ dl) {
    const int idx = blockIdx.x * blockDim.x + threadIdx.x;   // < G3*512
    const int row = idx >> 9;
    const int k   = idx & 511;
    const int g = row >> 9, j = row & 511;
    const float v = src[idx];
    const __nv_bfloat16 hi = __float2bfloat16(v);
    const __nv_bfloat16 lo = __float2bfloat16(v - __bfloat162float(hi));
    const size_t o = (size_t)(3 * j + g) * K512 + k;
    dh[o] = hi; dl[o] = lo;
}
__global__ void k_permb(const float* __restrict__ b1, float* __restrict__ d1,
                        const float* __restrict__ b2, float* __restrict__ d2,
                        const float* __restrict__ b3, float* __restrict__ d3,
                        const float* __restrict__ b4, float* __restrict__ d4) {
    const int idx = blockIdx.x * blockDim.x + threadIdx.x;
    const int g = idx >> 9, j = idx & 511;
    const int p = 3 * j + g;
    d1[p] = b1[idx]; d2[p] = b2[idx]; d3[p] = b3[idx]; d4[p] = b4[idx];
}
__global__ void k_init(const float* __restrict__ h1i, const float* __restrict__ h2i) {
    const int i = blockIdx.x * blockDim.x + threadIdx.x;
    g_h1x[0][i] = h1i[i];
    g_h2x[0][i] = h2i[i];
    if (i == 0) g_barcnt = 0;
}

// ---- FC head + finalize ----
__global__ void k_y(const float* __restrict__ Wfc, const float* __restrict__ bfc,
                    float* __restrict__ out) {
    const int w    = (blockIdx.x * blockDim.x + threadIdx.x) >> 5;
    const int lane = threadIdx.x & 31;
    const int b = w >> 6;
    const int t = w & (L - 1);
    const float* h2 = g_H2A + ((size_t)t * B + b) * H;
    float acc = 0.0f;
    #pragma unroll 4
    for (int j = lane; j < H; j += 32) acc += h2[j] * Wfc[j];
    #pragma unroll
    for (int o = 16; o; o >>= 1) acc += __shfl_xor_sync(0xffffffffu, acc, o);
    if (lane == 0) out[b * L + t] = acc + bfc[0];
}
__global__ void k_fin(float* __restrict__ out) {
    const int i = blockIdx.x * blockDim.x + threadIdx.x;
    out[B * L + i]         = g_h1x[0][i];
    out[B * L + B * H + i] = g_h2x[0][i];
}

// ---------------------------------------------------------------
extern "C" void kernel_launch(void* const* d_in, const int* in_sizes, int n_in,
                              void* d_out, int out_size)
{
    (void)in_sizes; (void)n_in; (void)out_size;
    const float* x    = (const float*)d_in[0];
    const float* h1i  = (const float*)d_in[1];
    const float* h2i  = (const float*)d_in[2];
    const float* Wih1 = (const float*)d_in[3];
    const float* Whh1 = (const float*)d_in[4];
    const float* bih1 = (const float*)d_in[5];
    const float* bhh1 = (const float*)d_in[6];
    const float* Wih2 = (const float*)d_in[7];
    const float* Whh2 = (const float*)d_in[8];
    const float* bih2 = (const float*)d_in[9];
    const float* bhh2 = (const float*)d_in[10];
    const float* Wfc  = (const float*)d_in[11];
    const float* bfc  = (const float*)d_in[12];
    float* out = (float*)d_out;

    const int PW = (G3 * K512) / 256;
    __nv_bfloat16 *d_Wih1h, *d_Wih1l, *d_Whh1h, *d_Whh1l;
    __nv_bfloat16 *d_Wih2h, *d_Wih2l, *d_Whh2h, *d_Whh2l;
    float *d_bih1p, *d_bhh1p, *d_bih2p, *d_bhh2p;
    cudaGetSymbolAddress((void**)&d_Wih1h, g_Wih1h);
    cudaGetSymbolAddress((void**)&d_Wih1l, g_Wih1l);
    cudaGetSymbolAddress((void**)&d_Whh1h, g_Whh1h);
    cudaGetSymbolAddress((void**)&d_Whh1l, g_Whh1l);
    cudaGetSymbolAddress((void**)&d_Wih2h, g_Wih2h);
    cudaGetSymbolAddress((void**)&d_Wih2l, g_Wih2l);
    cudaGetSymbolAddress((void**)&d_Whh2h, g_Whh2h);
    cudaGetSymbolAddress((void**)&d_Whh2l, g_Whh2l);
    cudaGetSymbolAddress((void**)&d_bih1p, g_bih1p);
    cudaGetSymbolAddress((void**)&d_bhh1p, g_bhh1p);
    cudaGetSymbolAddress((void**)&d_bih2p, g_bih2p);
    cudaGetSymbolAddress((void**)&d_bhh2p, g_bhh2p);

    k_perm<<<PW, 256>>>(Wih1, d_Wih1h, d_Wih1l);
    k_perm<<<PW, 256>>>(Whh1, d_Whh1h, d_Whh1l);
    k_perm<<<PW, 256>>>(Wih2, d_Wih2h, d_Wih2l);
    k_perm<<<PW, 256>>>(Whh2, d_Whh2h, d_Whh2l);
    k_permb<<<G3 / 256, 256>>>(bih1, d_bih1p, bhh1, d_bhh1p,
                               bih2, d_bih2p, bhh2, d_bhh2p);
    k_init<<<(B * H) / 256, 256>>>(h1i, h2i);

    k_gi1<<<dim3(G3 / TN, B / TM, L), 256, SMEM_DYN>>>(x, d_bih1p);

    k_loop<<<NCTA, 256, SMEM_DYN>>>();

    k_y  <<<(B * L * 32) / 256, 256>>>(Wfc, bfc, out);
    k_fin<<<(B * H) / 256, 256>>>(out);
}